// round 3
// baseline (speedup 1.0000x reference)
#include <cuda_runtime.h>
#include <math.h>

#define NN 100000
#define EE 1600000
#define CC 128
#define CAP 96
#define OUTC 10

// ---- scratch (device globals: no allocation allowed) ----
__device__ float g_Y[(size_t)NN * CC];        // x @ W_rel  (51.2 MB)
__device__ float g_R0[(size_t)NN * CC];       // ping      (51.2 MB)
__device__ float g_R1[(size_t)NN * CC];       // pong      (51.2 MB)
__device__ int   g_cnt[NN];
__device__ uint2 g_bucket[(size_t)NN * CAP];  // {src, weight-bits} per dst (76.8 MB)

// ---------------------------------------------------------------------------
// Edge preprocessing: bucket edges by destination (replaces all fp atomics)
// ---------------------------------------------------------------------------
__global__ void k_zero_cnt() {
    int i = blockIdx.x * blockDim.x + threadIdx.x;
    if (i < NN) g_cnt[i] = 0;
}

__global__ void k_bucket(const int* __restrict__ src, const int* __restrict__ dst,
                         const float* __restrict__ ew) {
    int e = blockIdx.x * blockDim.x + threadIdx.x;
    if (e >= EE) return;
    int d = dst[e];
    int s = atomicAdd(&g_cnt[d], 1);
    if (s < CAP)
        g_bucket[(size_t)d * CAP + s] = make_uint2((unsigned)src[e], __float_as_uint(ew[e]));
}

// ---------------------------------------------------------------------------
// Dual GEMM: Y = act(X) @ W_rel ; R = act(X) @ W_root + b
// CTA: 512 threads, M=32 rows, N=256 cols (Y|R), K=128.
// Warp w owns 16 cols; lane = row. A reads conflict-free (pad 129),
// B reads warp-uniform (broadcast). 100000 % 32 == 0 -> no tails.
// ---------------------------------------------------------------------------
#define GEMM_SMEM (32 * 129 * 4 + 128 * 256 * 4)

__global__ __launch_bounds__(512, 1)
void k_gemm_dual(const float* __restrict__ Xext,
                 int in_sel,              // 0: Xext, 1: g_R0, 2: g_R1 (with ReLU)
                 int out_sel,             // 0: R=g_R0, 1: R=g_R1
                 const float* __restrict__ Wrel,
                 const float* __restrict__ Wroot,
                 const float* __restrict__ bias)
{
    extern __shared__ float smem[];
    float (*As)[129] = (float (*)[129])smem;                 // [32][129]
    float (*Bs)[256] = (float (*)[256])(smem + 32 * 129);    // [128][256]

    const float* X = (in_sel == 0) ? Xext : (in_sel == 1 ? g_R0 : g_R1);
    float* R = out_sel ? g_R1 : g_R0;
    const int relu_in = (in_sel != 0);

    int tid  = threadIdx.x;
    int row0 = blockIdx.x * 32;

    // load X tile (32x128) -> As, fused ReLU
    #pragma unroll
    for (int i = 0; i < 2; i++) {
        int f4 = tid + i * 512;              // 0..1023 float4s
        int r = f4 >> 5, c4 = f4 & 31;
        float4 v = *(const float4*)(X + (size_t)(row0 + r) * CC + c4 * 4);
        if (relu_in) {
            v.x = fmaxf(v.x, 0.f); v.y = fmaxf(v.y, 0.f);
            v.z = fmaxf(v.z, 0.f); v.w = fmaxf(v.w, 0.f);
        }
        As[r][c4 * 4 + 0] = v.x; As[r][c4 * 4 + 1] = v.y;
        As[r][c4 * 4 + 2] = v.z; As[r][c4 * 4 + 3] = v.w;
    }
    // load both weight matrices -> Bs[k][0:128]=Wrel, Bs[k][128:256]=Wroot
    #pragma unroll
    for (int i = 0; i < 8; i++) {
        int f4 = tid + i * 512;              // 0..4095 float4s
        int k = f4 >> 5, c4 = f4 & 31;
        *(float4*)&Bs[k][c4 * 4]      = *(const float4*)(Wrel  + k * CC + c4 * 4);
        *(float4*)&Bs[k][CC + c4 * 4] = *(const float4*)(Wroot + k * CC + c4 * 4);
    }
    __syncthreads();

    int lane = tid & 31;
    int w    = tid >> 5;       // 0..15
    int c0   = w * 16;

    float acc[16];
    #pragma unroll
    for (int j = 0; j < 16; j++) acc[j] = 0.f;

    #pragma unroll 4
    for (int k = 0; k < CC; k++) {
        float a = As[lane][k];                 // conflict-free: bank=(lane+k)%32
        float4 b0 = *(const float4*)&Bs[k][c0 + 0];    // warp-uniform -> broadcast
        float4 b1 = *(const float4*)&Bs[k][c0 + 4];
        float4 b2 = *(const float4*)&Bs[k][c0 + 8];
        float4 b3 = *(const float4*)&Bs[k][c0 + 12];
        acc[0]  += a * b0.x; acc[1]  += a * b0.y; acc[2]  += a * b0.z; acc[3]  += a * b0.w;
        acc[4]  += a * b1.x; acc[5]  += a * b1.y; acc[6]  += a * b1.z; acc[7]  += a * b1.w;
        acc[8]  += a * b2.x; acc[9]  += a * b2.y; acc[10] += a * b2.z; acc[11] += a * b2.w;
        acc[12] += a * b3.x; acc[13] += a * b3.y; acc[14] += a * b3.z; acc[15] += a * b3.w;
    }

    int gr = row0 + lane;
    if (w < 8) {
        float4* yp = (float4*)(g_Y + (size_t)gr * CC + c0);
        #pragma unroll
        for (int j = 0; j < 4; j++)
            yp[j] = make_float4(acc[4*j], acc[4*j+1], acc[4*j+2], acc[4*j+3]);
    } else {
        int cr = c0 - CC;
        #pragma unroll
        for (int j = 0; j < 16; j++) acc[j] += __ldg(bias + cr + j);
        float4* rp = (float4*)(R + (size_t)gr * CC + cr);
        #pragma unroll
        for (int j = 0; j < 4; j++)
            rp[j] = make_float4(acc[4*j], acc[4*j+1], acc[4*j+2], acc[4*j+3]);
    }
}

// ---------------------------------------------------------------------------
// Aggregation: R[n] += sum_{e: dst=n} w_e * Y[src_e]   (warp per node)
// ---------------------------------------------------------------------------
__global__ __launch_bounds__(256)
void k_agg(int out_sel) {
    float* R = out_sel ? g_R1 : g_R0;
    int gw   = (blockIdx.x * blockDim.x + threadIdx.x) >> 5;
    int lane = threadIdx.x & 31;
    if (gw >= NN) return;

    int deg = min(g_cnt[gw], CAP);
    float4 acc = *(float4*)(R + (size_t)gw * CC + lane * 4);
    const uint2* bk = g_bucket + (size_t)gw * CAP;

    for (int base = 0; base < deg; base += 32) {
        int m = min(32, deg - base);
        uint2 e = make_uint2(0u, 0u);
        if (lane < m) e = bk[base + lane];
        for (int k = 0; k < m; k++) {
            int   s  = __shfl_sync(0xffffffffu, (int)e.x, k);
            float wt = __int_as_float(__shfl_sync(0xffffffffu, (int)e.y, k));
            float4 v = *(const float4*)(g_Y + (size_t)s * CC + lane * 4);
            acc.x += wt * v.x; acc.y += wt * v.y;
            acc.z += wt * v.z; acc.w += wt * v.w;
        }
    }
    *(float4*)(R + (size_t)gw * CC + lane * 4) = acc;
}

// ---------------------------------------------------------------------------
// Head: logits = relu(R0) @ W_lin + b ; log_softmax  (warp per node)
// ---------------------------------------------------------------------------
__global__ __launch_bounds__(256)
void k_head(const float* __restrict__ W, const float* __restrict__ b,
            float* __restrict__ out) {
    __shared__ float Wt[OUTC][CC];
    __shared__ float bs[OUTC];
    for (int i = threadIdx.x; i < OUTC * CC; i += 256) {
        int c = i / CC, j = i % CC;
        Wt[c][j] = W[j * OUTC + c];
    }
    if (threadIdx.x < OUTC) bs[threadIdx.x] = b[threadIdx.x];
    __syncthreads();

    int gw   = (blockIdx.x * blockDim.x + threadIdx.x) >> 5;
    int lane = threadIdx.x & 31;
    if (gw >= NN) return;

    float4 x = *(const float4*)(g_R0 + (size_t)gw * CC + lane * 4);
    x.x = fmaxf(x.x, 0.f); x.y = fmaxf(x.y, 0.f);
    x.z = fmaxf(x.z, 0.f); x.w = fmaxf(x.w, 0.f);

    float p[OUTC];
    #pragma unroll
    for (int c = 0; c < OUTC; c++) {
        float4 wv = *(const float4*)&Wt[c][lane * 4];
        float t = x.x * wv.x + x.y * wv.y + x.z * wv.z + x.w * wv.w;
        #pragma unroll
        for (int off = 16; off > 0; off >>= 1)
            t += __shfl_xor_sync(0xffffffffu, t, off);
        p[c] = t + bs[c];
    }
    float mx = p[0];
    #pragma unroll
    for (int c = 1; c < OUTC; c++) mx = fmaxf(mx, p[c]);
    float se = 0.f;
    #pragma unroll
    for (int c = 0; c < OUTC; c++) se += expf(p[c] - mx);
    float lse = mx + logf(se);
    if (lane == 0) {
        #pragma unroll
        for (int c = 0; c < OUTC; c++)
            out[(size_t)gw * OUTC + c] = p[c] - lse;
    }
}

// ---------------------------------------------------------------------------
extern "C" void kernel_launch(void* const* d_in, const int* in_sizes, int n_in,
                              void* d_out, int out_size) {
    const float* x0  = (const float*)d_in[0];
    const int*   ei  = (const int*)  d_in[1];   // [2, E]: row0 src, row1 dst
    const float* ew  = (const float*)d_in[2];
    const float* W1r = (const float*)d_in[3];
    const float* b1  = (const float*)d_in[4];
    const float* W1o = (const float*)d_in[5];
    const float* W2r = (const float*)d_in[6];
    const float* b2  = (const float*)d_in[7];
    const float* W2o = (const float*)d_in[8];
    const float* W3r = (const float*)d_in[9];
    const float* b3  = (const float*)d_in[10];
    const float* W3o = (const float*)d_in[11];
    const float* Wl  = (const float*)d_in[12];
    const float* bl  = (const float*)d_in[13];
    float* out = (float*)d_out;

    cudaFuncSetAttribute(k_gemm_dual, cudaFuncAttributeMaxDynamicSharedMemorySize,
                         GEMM_SMEM);

    // edge bucketing (shared by all 3 layers)
    k_zero_cnt<<<(NN + 255) / 256, 256>>>();
    k_bucket<<<(EE + 255) / 256, 256>>>(ei, ei + EE, ew);

    // layer 1: x0 -> (Y, R0); scatter into R0
    k_gemm_dual<<<NN / 32, 512, GEMM_SMEM>>>(x0, 0, 0, W1r, W1o, b1);
    k_agg<<<NN / 8, 256>>>(0);
    // layer 2: relu(R0) -> (Y, R1); scatter into R1
    k_gemm_dual<<<NN / 32, 512, GEMM_SMEM>>>(nullptr, 1, 1, W2r, W2o, b2);
    k_agg<<<NN / 8, 256>>>(1);
    // layer 3: relu(R1) -> (Y, R0); scatter into R0
    k_gemm_dual<<<NN / 32, 512, GEMM_SMEM>>>(nullptr, 2, 0, W3r, W3o, b3);
    k_agg<<<NN / 8, 256>>>(0);
    // head
    k_head<<<NN / 8, 256>>>(Wl, bl, out);
}

// round 4
// speedup vs baseline: 1.6824x; 1.6824x over previous
#include <cuda_runtime.h>
#include <math.h>

#define NN 100000
#define EE 1600000
#define CC 128
#define CAP 96
#define OUTC 10

// ---- scratch (device globals: no allocation allowed) ----
__device__ float g_Y[(size_t)NN * CC];        // x @ W_rel
__device__ float g_R0[(size_t)NN * CC];       // ping
__device__ float g_R1[(size_t)NN * CC];       // pong
__device__ int   g_cnt[NN];
__device__ uint2 g_bucket[(size_t)NN * CAP];  // {src, weight-bits} per dst

// ---------------------------------------------------------------------------
// Edge preprocessing: bucket edges by destination
// ---------------------------------------------------------------------------
__global__ void k_zero_cnt() {
    int i = blockIdx.x * blockDim.x + threadIdx.x;
    if (i < NN) g_cnt[i] = 0;
}

__global__ void k_bucket(const int* __restrict__ src, const int* __restrict__ dst,
                         const float* __restrict__ ew) {
    int e = blockIdx.x * blockDim.x + threadIdx.x;
    if (e >= EE) return;
    int d = dst[e];
    int s = atomicAdd(&g_cnt[d], 1);
    if (s < CAP)
        g_bucket[(size_t)d * CAP + s] = make_uint2((unsigned)src[e], __float_as_uint(ew[e]));
}

// ---------------------------------------------------------------------------
// 3xTF32 tensor-core dual GEMM.
//   grid = (782, 4): blockIdx.y 0..1 -> Y = act(X)@Wrel   cols by*64
//                    blockIdx.y 2..3 -> R = act(X)@Wroot + b, cols (by-2)*64
//   CTA: 256 thr (8 warps), tile M=128 x N=64, K=128 fully staged in smem.
//   Warp tile 32x32 -> 2(m) x 4(n) m16n8k8 tiles. 3 mma passes (Ah*Bh + Ah*Bl + Al*Bh).
// ---------------------------------------------------------------------------
#define AP 132   // A row pad: bank = (4r + c) % 32, all-distinct
#define BP 72    // B row pad: bank = (8k + n) % 32, all-distinct
#define GEMM_SMEM (128 * AP * 4 + 128 * BP * 4)   // 67584 + 36864 = 104448 B

__device__ __forceinline__ void split_tf32(float x, unsigned& hi, unsigned& lo) {
    unsigned h;
    asm("cvt.rna.tf32.f32 %0, %1;" : "=r"(h) : "f"(x));
    float l = x - __uint_as_float(h);
    unsigned lr;
    asm("cvt.rna.tf32.f32 %0, %1;" : "=r"(lr) : "f"(l));
    hi = h; lo = lr;
}

__device__ __forceinline__ void mma_tf32(float4& d,
                                         const unsigned a[4], const unsigned b[2]) {
    asm volatile(
        "mma.sync.aligned.m16n8k8.row.col.f32.tf32.tf32.f32 "
        "{%0,%1,%2,%3}, {%4,%5,%6,%7}, {%8,%9}, {%0,%1,%2,%3};\n"
        : "+f"(d.x), "+f"(d.y), "+f"(d.z), "+f"(d.w)
        : "r"(a[0]), "r"(a[1]), "r"(a[2]), "r"(a[3]), "r"(b[0]), "r"(b[1]));
}

__global__ __launch_bounds__(256, 1)
void k_gemm_dual(const float* __restrict__ Xext,
                 int in_sel,              // 0: Xext, 1: g_R0 (ReLU), 2: g_R1 (ReLU)
                 int out_sel,             // 0: R=g_R0, 1: R=g_R1
                 const float* __restrict__ Wrel,
                 const float* __restrict__ Wroot,
                 const float* __restrict__ bias)
{
    extern __shared__ float smem[];
    float (*As)[AP] = (float (*)[AP])smem;             // [128][132]
    float (*Bs)[BP] = (float (*)[BP])(smem + 128 * AP); // [128][72] (64 used)

    const float* X = (in_sel == 0) ? Xext : (in_sel == 1 ? g_R0 : g_R1);
    const int relu_in = (in_sel != 0);
    const int by = blockIdx.y;
    const int is_root = (by >= 2);
    const int ocol = is_root ? (by - 2) * 64 : by * 64;
    const float* W = (is_root ? Wroot : Wrel) + ocol;
    float* O = is_root ? (out_sel ? g_R1 : g_R0) : g_Y;

    const int tid  = threadIdx.x;
    const int row0 = blockIdx.x * 128;

    // ---- stage A (128x128, ReLU-fused, zero-fill OOB rows) ----
    #pragma unroll
    for (int i = 0; i < 16; i++) {
        int f4 = tid + i * 256;            // 0..4095
        int r = f4 >> 5, c4 = f4 & 31;
        float4 v = make_float4(0.f, 0.f, 0.f, 0.f);
        if (row0 + r < NN)
            v = *(const float4*)(X + (size_t)(row0 + r) * CC + c4 * 4);
        if (relu_in) {
            v.x = fmaxf(v.x, 0.f); v.y = fmaxf(v.y, 0.f);
            v.z = fmaxf(v.z, 0.f); v.w = fmaxf(v.w, 0.f);
        }
        *(float4*)&As[r][c4 * 4] = v;
    }
    // ---- stage B (128 x 64) ----
    #pragma unroll
    for (int i = 0; i < 8; i++) {
        int f4 = tid + i * 256;            // 0..2047
        int k = f4 >> 4, n4 = f4 & 15;
        *(float4*)&Bs[k][n4 * 4] = *(const float4*)(W + (size_t)k * CC + n4 * 4);
    }
    __syncthreads();

    const int lane = tid & 31;
    const int w    = tid >> 5;         // 0..7
    const int wm   = w >> 1;           // 0..3 : rows wm*32
    const int wn   = w & 1;            // 0..1 : cols wn*32
    const int gr   = lane >> 2;        // 0..7
    const int tg   = lane & 3;         // 0..3

    float4 acc[2][4];
    #pragma unroll
    for (int mt = 0; mt < 2; mt++)
        #pragma unroll
        for (int nt = 0; nt < 4; nt++)
            acc[mt][nt] = make_float4(0.f, 0.f, 0.f, 0.f);

    #pragma unroll 4
    for (int ks = 0; ks < 16; ks++) {
        const int k0 = ks * 8;
        unsigned ah[2][4], al[2][4], bh[4][2], bl[4][2];
        #pragma unroll
        for (int mt = 0; mt < 2; mt++) {
            int r = wm * 32 + mt * 16 + gr;
            split_tf32(As[r    ][k0 + tg    ], ah[mt][0], al[mt][0]);
            split_tf32(As[r + 8][k0 + tg    ], ah[mt][1], al[mt][1]);
            split_tf32(As[r    ][k0 + tg + 4], ah[mt][2], al[mt][2]);
            split_tf32(As[r + 8][k0 + tg + 4], ah[mt][3], al[mt][3]);
        }
        #pragma unroll
        for (int nt = 0; nt < 4; nt++) {
            int n = wn * 32 + nt * 8 + gr;
            split_tf32(Bs[k0 + tg    ][n], bh[nt][0], bl[nt][0]);
            split_tf32(Bs[k0 + tg + 4][n], bh[nt][1], bl[nt][1]);
        }
        #pragma unroll
        for (int mt = 0; mt < 2; mt++)
            #pragma unroll
            for (int nt = 0; nt < 4; nt++) {
                mma_tf32(acc[mt][nt], ah[mt], bl[nt]);   // small terms first
                mma_tf32(acc[mt][nt], al[mt], bh[nt]);
                mma_tf32(acc[mt][nt], ah[mt], bh[nt]);
            }
    }

    // ---- epilogue ----
    #pragma unroll
    for (int mt = 0; mt < 2; mt++) {
        #pragma unroll
        for (int nt = 0; nt < 4; nt++) {
            int cl = wn * 32 + nt * 8 + tg * 2;      // local col (pair)
            int cg = ocol + cl;                      // col in 128-wide output
            float2 lo = make_float2(acc[mt][nt].x, acc[mt][nt].y);
            float2 hi = make_float2(acc[mt][nt].z, acc[mt][nt].w);
            if (is_root) {
                float b0 = __ldg(bias + cg), b1 = __ldg(bias + cg + 1);
                lo.x += b0; lo.y += b1; hi.x += b0; hi.y += b1;
            }
            int r = row0 + wm * 32 + mt * 16 + gr;
            if (r < NN)     *(float2*)(O + (size_t)r * CC + cg) = lo;
            if (r + 8 < NN) *(float2*)(O + (size_t)(r + 8) * CC + cg) = hi;
        }
    }
}

// ---------------------------------------------------------------------------
// Aggregation: R[n] += sum_{e: dst=n} w_e * Y[src_e]   (warp per node)
// Unrolled x4 with dual accumulators for MLP=4.
// ---------------------------------------------------------------------------
__global__ __launch_bounds__(256)
void k_agg(int out_sel) {
    float* R = out_sel ? g_R1 : g_R0;
    int gw   = (blockIdx.x * blockDim.x + threadIdx.x) >> 5;
    int lane = threadIdx.x & 31;
    if (gw >= NN) return;

    int deg = min(g_cnt[gw], CAP);
    float4 acc0 = *(float4*)(R + (size_t)gw * CC + lane * 4);
    float4 acc1 = make_float4(0.f, 0.f, 0.f, 0.f);
    const uint2* bk = g_bucket + (size_t)gw * CAP;

    for (int base = 0; base < deg; base += 32) {
        int m = min(32, deg - base);
        uint2 e = make_uint2(0u, 0u);
        if (lane < m) e = bk[base + lane];
        int k = 0;
        for (; k + 4 <= m; k += 4) {
            int   s0 = __shfl_sync(0xffffffffu, (int)e.x, k);
            int   s1 = __shfl_sync(0xffffffffu, (int)e.x, k + 1);
            int   s2 = __shfl_sync(0xffffffffu, (int)e.x, k + 2);
            int   s3 = __shfl_sync(0xffffffffu, (int)e.x, k + 3);
            float w0 = __int_as_float(__shfl_sync(0xffffffffu, (int)e.y, k));
            float w1 = __int_as_float(__shfl_sync(0xffffffffu, (int)e.y, k + 1));
            float w2 = __int_as_float(__shfl_sync(0xffffffffu, (int)e.y, k + 2));
            float w3 = __int_as_float(__shfl_sync(0xffffffffu, (int)e.y, k + 3));
            float4 v0 = *(const float4*)(g_Y + (size_t)s0 * CC + lane * 4);
            float4 v1 = *(const float4*)(g_Y + (size_t)s1 * CC + lane * 4);
            float4 v2 = *(const float4*)(g_Y + (size_t)s2 * CC + lane * 4);
            float4 v3 = *(const float4*)(g_Y + (size_t)s3 * CC + lane * 4);
            acc0.x += w0 * v0.x; acc0.y += w0 * v0.y; acc0.z += w0 * v0.z; acc0.w += w0 * v0.w;
            acc1.x += w1 * v1.x; acc1.y += w1 * v1.y; acc1.z += w1 * v1.z; acc1.w += w1 * v1.w;
            acc0.x += w2 * v2.x; acc0.y += w2 * v2.y; acc0.z += w2 * v2.z; acc0.w += w2 * v2.w;
            acc1.x += w3 * v3.x; acc1.y += w3 * v3.y; acc1.z += w3 * v3.z; acc1.w += w3 * v3.w;
        }
        for (; k < m; k++) {
            int   s  = __shfl_sync(0xffffffffu, (int)e.x, k);
            float wt = __int_as_float(__shfl_sync(0xffffffffu, (int)e.y, k));
            float4 v = *(const float4*)(g_Y + (size_t)s * CC + lane * 4);
            acc0.x += wt * v.x; acc0.y += wt * v.y;
            acc0.z += wt * v.z; acc0.w += wt * v.w;
        }
    }
    acc0.x += acc1.x; acc0.y += acc1.y; acc0.z += acc1.z; acc0.w += acc1.w;
    *(float4*)(R + (size_t)gw * CC + lane * 4) = acc0;
}

// ---------------------------------------------------------------------------
// Head: logits = relu(R0) @ W_lin + b ; log_softmax  (warp per node)
// ---------------------------------------------------------------------------
__global__ __launch_bounds__(256)
void k_head(const float* __restrict__ W, const float* __restrict__ b,
            float* __restrict__ out) {
    __shared__ float Wt[OUTC][CC];
    __shared__ float bs[OUTC];
    for (int i = threadIdx.x; i < OUTC * CC; i += 256) {
        int c = i / CC, j = i % CC;
        Wt[c][j] = W[j * OUTC + c];
    }
    if (threadIdx.x < OUTC) bs[threadIdx.x] = b[threadIdx.x];
    __syncthreads();

    int gw   = (blockIdx.x * blockDim.x + threadIdx.x) >> 5;
    int lane = threadIdx.x & 31;
    if (gw >= NN) return;

    float4 x = *(const float4*)(g_R0 + (size_t)gw * CC + lane * 4);
    x.x = fmaxf(x.x, 0.f); x.y = fmaxf(x.y, 0.f);
    x.z = fmaxf(x.z, 0.f); x.w = fmaxf(x.w, 0.f);

    float p[OUTC];
    #pragma unroll
    for (int c = 0; c < OUTC; c++) {
        float4 wv = *(const float4*)&Wt[c][lane * 4];
        float t = x.x * wv.x + x.y * wv.y + x.z * wv.z + x.w * wv.w;
        #pragma unroll
        for (int off = 16; off > 0; off >>= 1)
            t += __shfl_xor_sync(0xffffffffu, t, off);
        p[c] = t + bs[c];
    }
    float mx = p[0];
    #pragma unroll
    for (int c = 1; c < OUTC; c++) mx = fmaxf(mx, p[c]);
    float se = 0.f;
    #pragma unroll
    for (int c = 0; c < OUTC; c++) se += expf(p[c] - mx);
    float lse = mx + logf(se);
    if (lane == 0) {
        #pragma unroll
        for (int c = 0; c < OUTC; c++)
            out[(size_t)gw * OUTC + c] = p[c] - lse;
    }
}

// ---------------------------------------------------------------------------
extern "C" void kernel_launch(void* const* d_in, const int* in_sizes, int n_in,
                              void* d_out, int out_size) {
    const float* x0  = (const float*)d_in[0];
    const int*   ei  = (const int*)  d_in[1];
    const float* ew  = (const float*)d_in[2];
    const float* W1r = (const float*)d_in[3];
    const float* b1  = (const float*)d_in[4];
    const float* W1o = (const float*)d_in[5];
    const float* W2r = (const float*)d_in[6];
    const float* b2  = (const float*)d_in[7];
    const float* W2o = (const float*)d_in[8];
    const float* W3r = (const float*)d_in[9];
    const float* b3  = (const float*)d_in[10];
    const float* W3o = (const float*)d_in[11];
    const float* Wl  = (const float*)d_in[12];
    const float* bl  = (const float*)d_in[13];
    float* out = (float*)d_out;

    cudaFuncSetAttribute(k_gemm_dual, cudaFuncAttributeMaxDynamicSharedMemorySize,
                         GEMM_SMEM);

    // edge bucketing (shared by all 3 layers)
    k_zero_cnt<<<(NN + 255) / 256, 256>>>();
    k_bucket<<<(EE + 255) / 256, 256>>>(ei, ei + EE, ew);

    dim3 ggrid((NN + 127) / 128, 4);   // 782 x 4

    // layer 1: x0 -> (Y, R0); scatter into R0
    k_gemm_dual<<<ggrid, 256, GEMM_SMEM>>>(x0, 0, 0, W1r, W1o, b1);
    k_agg<<<NN / 8, 256>>>(0);
    // layer 2: relu(R0) -> (Y, R1); scatter into R1
    k_gemm_dual<<<ggrid, 256, GEMM_SMEM>>>(nullptr, 1, 1, W2r, W2o, b2);
    k_agg<<<NN / 8, 256>>>(1);
    // layer 3: relu(R1) -> (Y, R0); scatter into R0
    k_gemm_dual<<<ggrid, 256, GEMM_SMEM>>>(nullptr, 2, 0, W3r, W3o, b3);
    k_agg<<<NN / 8, 256>>>(0);
    // head
    k_head<<<NN / 8, 256>>>(Wl, bl, out);
}

// round 5
// speedup vs baseline: 2.3465x; 1.3947x over previous
#include <cuda_runtime.h>
#include <cuda_fp16.h>
#include <math.h>

#define NN 100000
#define EE 1600000
#define CC 128
#define CAP 96
#define OUTC 10

// ---- scratch (device globals: no allocation allowed) ----
__device__ __half g_Yh[(size_t)NN * CC];      // x @ W_rel, fp16 (25.6 MB, L2-resident)
__device__ float  g_R0[(size_t)NN * CC];      // ping
__device__ float  g_R1[(size_t)NN * CC];      // pong
__device__ int    g_cnt[NN];
__device__ uint2  g_bucket[(size_t)NN * CAP]; // {src, weight-bits} per dst

// ---------------------------------------------------------------------------
// Edge preprocessing: bucket edges by destination
// ---------------------------------------------------------------------------
__global__ void k_zero_cnt() {
    int i = blockIdx.x * blockDim.x + threadIdx.x;
    if (i < NN) g_cnt[i] = 0;
}

__global__ void k_bucket(const int* __restrict__ src, const int* __restrict__ dst,
                         const float* __restrict__ ew) {
    int e = blockIdx.x * blockDim.x + threadIdx.x;
    if (e >= EE) return;
    int d = dst[e];
    int s = atomicAdd(&g_cnt[d], 1);
    if (s < CAP)
        g_bucket[(size_t)d * CAP + s] = make_uint2((unsigned)src[e], __float_as_uint(ew[e]));
}

// ---------------------------------------------------------------------------
// 3x-bf16 tensor-core dual GEMM (m16n8k16).
//   grid = (782, 4): by 0..1 -> Y = act(X)@Wrel (fp16 out), cols by*64
//                    by 2..3 -> R = act(X)@Wroot + b (fp32), cols (by-2)*64
//   CTA: 256 thr (8 warps), tile M=128 x N=64, K=128 fully staged in smem.
//   Warp tile 32x32 -> 2(m) x 4(n) m16n8k16 tiles, 8 k-steps of K=16.
//   3 mma passes: Ah*Bl + Al*Bh + Ah*Bh (drop Al*Bl ~ 2^-16).
// ---------------------------------------------------------------------------
#define AP 132   // A pad: float2 A reads near-conflict-free
#define BPW 68   // B pad: scalar B reads: bank = (8*tg + gr + c) % 32, all distinct
#define GEMM_SMEM (128 * AP * 4 + 128 * BPW * 4)   // 67584 + 34816 = 102400 B

// pack two consecutive-k fp32 values into bf16x2 hi + bf16x2 lo (residual)
__device__ __forceinline__ void split2_bf16(float x0, float x1,
                                            unsigned& h, unsigned& l) {
    asm("cvt.rn.bf16x2.f32 %0, %1, %2;" : "=r"(h) : "f"(x1), "f"(x0));
    float h0 = __uint_as_float(h << 16);
    float h1 = __uint_as_float(h & 0xffff0000u);
    float l0 = x0 - h0, l1 = x1 - h1;
    asm("cvt.rn.bf16x2.f32 %0, %1, %2;" : "=r"(l) : "f"(l1), "f"(l0));
}

__device__ __forceinline__ void mma_bf16(float4& d,
                                         const unsigned a[4], const unsigned b[2]) {
    asm volatile(
        "mma.sync.aligned.m16n8k16.row.col.f32.bf16.bf16.f32 "
        "{%0,%1,%2,%3}, {%4,%5,%6,%7}, {%8,%9}, {%0,%1,%2,%3};\n"
        : "+f"(d.x), "+f"(d.y), "+f"(d.z), "+f"(d.w)
        : "r"(a[0]), "r"(a[1]), "r"(a[2]), "r"(a[3]), "r"(b[0]), "r"(b[1]));
}

__global__ __launch_bounds__(256, 1)
void k_gemm_dual(const float* __restrict__ Xext,
                 int in_sel,              // 0: Xext, 1: g_R0 (ReLU), 2: g_R1 (ReLU)
                 int out_sel,             // 0: R=g_R0, 1: R=g_R1
                 const float* __restrict__ Wrel,
                 const float* __restrict__ Wroot,
                 const float* __restrict__ bias)
{
    extern __shared__ float smem[];
    float (*As)[AP]  = (float (*)[AP])smem;               // [128][132]
    float (*Bs)[BPW] = (float (*)[BPW])(smem + 128 * AP); // [128][68] (64 used)

    const float* X = (in_sel == 0) ? Xext : (in_sel == 1 ? g_R0 : g_R1);
    const int relu_in = (in_sel != 0);
    const int by = blockIdx.y;
    const int is_root = (by >= 2);
    const int ocol = is_root ? (by - 2) * 64 : by * 64;
    const float* W = (is_root ? Wroot : Wrel) + ocol;

    const int tid  = threadIdx.x;
    const int row0 = blockIdx.x * 128;

    // ---- stage A (128x128, ReLU-fused, zero-fill OOB rows) ----
    #pragma unroll
    for (int i = 0; i < 16; i++) {
        int f4 = tid + i * 256;
        int r = f4 >> 5, c4 = f4 & 31;
        float4 v = make_float4(0.f, 0.f, 0.f, 0.f);
        if (row0 + r < NN)
            v = *(const float4*)(X + (size_t)(row0 + r) * CC + c4 * 4);
        if (relu_in) {
            v.x = fmaxf(v.x, 0.f); v.y = fmaxf(v.y, 0.f);
            v.z = fmaxf(v.z, 0.f); v.w = fmaxf(v.w, 0.f);
        }
        *(float4*)&As[r][c4 * 4] = v;
    }
    // ---- stage B (128 x 64) ----
    #pragma unroll
    for (int i = 0; i < 8; i++) {
        int f4 = tid + i * 256;
        int k = f4 >> 4, n4 = f4 & 15;
        *(float4*)&Bs[k][n4 * 4] = *(const float4*)(W + (size_t)k * CC + n4 * 4);
    }
    __syncthreads();

    const int lane = tid & 31;
    const int w    = tid >> 5;         // 0..7
    const int wm   = w >> 1;           // 0..3 : rows wm*32
    const int wn   = w & 1;            // 0..1 : cols wn*32
    const int gr   = lane >> 2;        // 0..7
    const int tg   = lane & 3;         // 0..3

    float4 acc[2][4];
    #pragma unroll
    for (int mt = 0; mt < 2; mt++)
        #pragma unroll
        for (int nt = 0; nt < 4; nt++)
            acc[mt][nt] = make_float4(0.f, 0.f, 0.f, 0.f);

    #pragma unroll
    for (int ks = 0; ks < 8; ks++) {
        const int k0 = ks * 16;
        unsigned ah[2][4], al[2][4], bh[4][2], bl[4][2];
        #pragma unroll
        for (int mt = 0; mt < 2; mt++) {
            int r = wm * 32 + mt * 16 + gr;
            float2 x0 = *(const float2*)&As[r    ][k0 + 2 * tg];
            float2 x1 = *(const float2*)&As[r + 8][k0 + 2 * tg];
            float2 x2 = *(const float2*)&As[r    ][k0 + 2 * tg + 8];
            float2 x3 = *(const float2*)&As[r + 8][k0 + 2 * tg + 8];
            split2_bf16(x0.x, x0.y, ah[mt][0], al[mt][0]);
            split2_bf16(x1.x, x1.y, ah[mt][1], al[mt][1]);
            split2_bf16(x2.x, x2.y, ah[mt][2], al[mt][2]);
            split2_bf16(x3.x, x3.y, ah[mt][3], al[mt][3]);
        }
        #pragma unroll
        for (int nt = 0; nt < 4; nt++) {
            int n = wn * 32 + nt * 8 + gr;
            float y0 = Bs[k0 + 2 * tg    ][n], y1 = Bs[k0 + 2 * tg + 1][n];
            float y2 = Bs[k0 + 2 * tg + 8][n], y3 = Bs[k0 + 2 * tg + 9][n];
            split2_bf16(y0, y1, bh[nt][0], bl[nt][0]);
            split2_bf16(y2, y3, bh[nt][1], bl[nt][1]);
        }
        #pragma unroll
        for (int mt = 0; mt < 2; mt++)
            #pragma unroll
            for (int nt = 0; nt < 4; nt++) {
                mma_bf16(acc[mt][nt], ah[mt], bl[nt]);   // small terms first
                mma_bf16(acc[mt][nt], al[mt], bh[nt]);
                mma_bf16(acc[mt][nt], ah[mt], bh[nt]);
            }
    }

    // ---- epilogue ----
    float* Rout = out_sel ? g_R1 : g_R0;
    #pragma unroll
    for (int mt = 0; mt < 2; mt++) {
        #pragma unroll
        for (int nt = 0; nt < 4; nt++) {
            int cl = wn * 32 + nt * 8 + tg * 2;
            int cg = ocol + cl;
            int r  = row0 + wm * 32 + mt * 16 + gr;
            if (is_root) {
                float b0 = __ldg(bias + cg), b1 = __ldg(bias + cg + 1);
                if (r < NN)
                    *(float2*)(Rout + (size_t)r * CC + cg) =
                        make_float2(acc[mt][nt].x + b0, acc[mt][nt].y + b1);
                if (r + 8 < NN)
                    *(float2*)(Rout + (size_t)(r + 8) * CC + cg) =
                        make_float2(acc[mt][nt].z + b0, acc[mt][nt].w + b1);
            } else {
                if (r < NN)
                    *(__half2*)(g_Yh + (size_t)r * CC + cg) =
                        __floats2half2_rn(acc[mt][nt].x, acc[mt][nt].y);
                if (r + 8 < NN)
                    *(__half2*)(g_Yh + (size_t)(r + 8) * CC + cg) =
                        __floats2half2_rn(acc[mt][nt].z, acc[mt][nt].w);
            }
        }
    }
}

// ---------------------------------------------------------------------------
// Aggregation: R[n] += sum_{e: dst=n} w_e * Yh[src_e]   (warp per node)
// fp16 gather (256B/edge), x2 unroll with dual accumulators.
// ---------------------------------------------------------------------------
__global__ __launch_bounds__(256)
void k_agg(int out_sel) {
    float* R = out_sel ? g_R1 : g_R0;
    int gw   = (blockIdx.x * blockDim.x + threadIdx.x) >> 5;
    int lane = threadIdx.x & 31;
    if (gw >= NN) return;

    int deg = min(g_cnt[gw], CAP);
    float4 acc0 = *(float4*)(R + (size_t)gw * CC + lane * 4);
    float4 acc1 = make_float4(0.f, 0.f, 0.f, 0.f);
    const uint2* bk = g_bucket + (size_t)gw * CAP;

    for (int base = 0; base < deg; base += 32) {
        int m = min(32, deg - base);
        uint2 e = make_uint2(0u, 0u);
        if (lane < m) e = bk[base + lane];
        int k = 0;
        for (; k + 2 <= m; k += 2) {
            int   s0 = __shfl_sync(0xffffffffu, (int)e.x, k);
            int   s1 = __shfl_sync(0xffffffffu, (int)e.x, k + 1);
            float w0 = __int_as_float(__shfl_sync(0xffffffffu, (int)e.y, k));
            float w1 = __int_as_float(__shfl_sync(0xffffffffu, (int)e.y, k + 1));
            uint2 p0 = *(const uint2*)(g_Yh + (size_t)s0 * CC + lane * 4);
            uint2 p1 = *(const uint2*)(g_Yh + (size_t)s1 * CC + lane * 4);
            float2 a0 = __half22float2(*(const __half2*)&p0.x);
            float2 a1 = __half22float2(*(const __half2*)&p0.y);
            float2 c0 = __half22float2(*(const __half2*)&p1.x);
            float2 c1 = __half22float2(*(const __half2*)&p1.y);
            acc0.x += w0 * a0.x; acc0.y += w0 * a0.y;
            acc0.z += w0 * a1.x; acc0.w += w0 * a1.y;
            acc1.x += w1 * c0.x; acc1.y += w1 * c0.y;
            acc1.z += w1 * c1.x; acc1.w += w1 * c1.y;
        }
        if (k < m) {
            int   s  = __shfl_sync(0xffffffffu, (int)e.x, k);
            float wt = __int_as_float(__shfl_sync(0xffffffffu, (int)e.y, k));
            uint2 p  = *(const uint2*)(g_Yh + (size_t)s * CC + lane * 4);
            float2 a0 = __half22float2(*(const __half2*)&p.x);
            float2 a1 = __half22float2(*(const __half2*)&p.y);
            acc0.x += wt * a0.x; acc0.y += wt * a0.y;
            acc0.z += wt * a1.x; acc0.w += wt * a1.y;
        }
    }
    acc0.x += acc1.x; acc0.y += acc1.y; acc0.z += acc1.z; acc0.w += acc1.w;
    *(float4*)(R + (size_t)gw * CC + lane * 4) = acc0;
}

// ---------------------------------------------------------------------------
// Head: logits = relu(R0) @ W_lin + b ; log_softmax  (warp per node)
// ---------------------------------------------------------------------------
__global__ __launch_bounds__(256)
void k_head(const float* __restrict__ W, const float* __restrict__ b,
            float* __restrict__ out) {
    __shared__ float Wt[OUTC][CC];
    __shared__ float bs[OUTC];
    for (int i = threadIdx.x; i < OUTC * CC; i += 256) {
        int c = i / CC, j = i % CC;
        Wt[c][j] = W[j * OUTC + c];
    }
    if (threadIdx.x < OUTC) bs[threadIdx.x] = b[threadIdx.x];
    __syncthreads();

    int gw   = (blockIdx.x * blockDim.x + threadIdx.x) >> 5;
    int lane = threadIdx.x & 31;
    if (gw >= NN) return;

    float4 x = *(const float4*)(g_R0 + (size_t)gw * CC + lane * 4);
    x.x = fmaxf(x.x, 0.f); x.y = fmaxf(x.y, 0.f);
    x.z = fmaxf(x.z, 0.f); x.w = fmaxf(x.w, 0.f);

    float p[OUTC];
    #pragma unroll
    for (int c = 0; c < OUTC; c++) {
        float4 wv = *(const float4*)&Wt[c][lane * 4];
        float t = x.x * wv.x + x.y * wv.y + x.z * wv.z + x.w * wv.w;
        #pragma unroll
        for (int off = 16; off > 0; off >>= 1)
            t += __shfl_xor_sync(0xffffffffu, t, off);
        p[c] = t + bs[c];
    }
    float mx = p[0];
    #pragma unroll
    for (int c = 1; c < OUTC; c++) mx = fmaxf(mx, p[c]);
    float se = 0.f;
    #pragma unroll
    for (int c = 0; c < OUTC; c++) se += expf(p[c] - mx);
    float lse = mx + logf(se);
    if (lane == 0) {
        #pragma unroll
        for (int c = 0; c < OUTC; c++)
            out[(size_t)gw * OUTC + c] = p[c] - lse;
    }
}

// ---------------------------------------------------------------------------
extern "C" void kernel_launch(void* const* d_in, const int* in_sizes, int n_in,
                              void* d_out, int out_size) {
    const float* x0  = (const float*)d_in[0];
    const int*   ei  = (const int*)  d_in[1];
    const float* ew  = (const float*)d_in[2];
    const float* W1r = (const float*)d_in[3];
    const float* b1  = (const float*)d_in[4];
    const float* W1o = (const float*)d_in[5];
    const float* W2r = (const float*)d_in[6];
    const float* b2  = (const float*)d_in[7];
    const float* W2o = (const float*)d_in[8];
    const float* W3r = (const float*)d_in[9];
    const float* b3  = (const float*)d_in[10];
    const float* W3o = (const float*)d_in[11];
    const float* Wl  = (const float*)d_in[12];
    const float* bl  = (const float*)d_in[13];
    float* out = (float*)d_out;

    cudaFuncSetAttribute(k_gemm_dual, cudaFuncAttributeMaxDynamicSharedMemorySize,
                         GEMM_SMEM);

    // edge bucketing (shared by all 3 layers)
    k_zero_cnt<<<(NN + 255) / 256, 256>>>();
    k_bucket<<<(EE + 255) / 256, 256>>>(ei, ei + EE, ew);

    dim3 ggrid((NN + 127) / 128, 4);   // 782 x 4

    // layer 1: x0 -> (Yh, R0); scatter into R0
    k_gemm_dual<<<ggrid, 256, GEMM_SMEM>>>(x0, 0, 0, W1r, W1o, b1);
    k_agg<<<NN / 8, 256>>>(0);
    // layer 2: relu(R0) -> (Yh, R1); scatter into R1
    k_gemm_dual<<<ggrid, 256, GEMM_SMEM>>>(nullptr, 1, 1, W2r, W2o, b2);
    k_agg<<<NN / 8, 256>>>(1);
    // layer 3: relu(R1) -> (Yh, R0); scatter into R0
    k_gemm_dual<<<ggrid, 256, GEMM_SMEM>>>(nullptr, 2, 0, W3r, W3o, b3);
    k_agg<<<NN / 8, 256>>>(0);
    // head
    k_head<<<NN / 8, 256>>>(Wl, bl, out);
}